// round 2
// baseline (speedup 1.0000x reference)
#include <cuda_runtime.h>
#include <cstddef>

#define Bn  4
#define NHn 8
#define Cn  32
#define Hn  128
#define Wn  128
#define HWn (Hn*Wn)
#define CDn 256

// ---------------- scratch (device globals; no allocation allowed) ----------------
__device__ __align__(16) float g_qp [Bn*HWn*Cn];           // NHWC
__device__ __align__(16) float g_pc [Bn*HWn*Cn];           // NHWC
__device__ __align__(16) float g_xi [Bn*NHn*HWn*Cn];       // per-image NHWC (img = b*8+n)
__device__ __align__(16) float g_cat[(size_t)Bn*NHn*HWn*96]; // per-image NHWC-96: [x112|x223|x33]

__device__ __align__(16) float g_w1 [NHn*9*Cn*96];   // [h][tap][ci][co]  scale-folded
__device__ __align__(16) float g_b1 [NHn*96];
__device__ __align__(16) float g_w2 [NHn*9*Cn*64];
__device__ __align__(16) float g_b2 [NHn*64];
__device__ __align__(16) float g_w3k[NHn*9*Cn*32];
__device__ __align__(16) float g_b3k[NHn*32];
__device__ __align__(16) float g_wc [NHn*96*32];     // [h][cin][co]      scale-folded
__device__ __align__(16) float g_bc [NHn*32];
__device__ __align__(16) float g_wv [CDn*Cn];        // [ci][co]          scale-folded
__device__ __align__(16) float g_wvb[Cn];

// ---------------- helpers ----------------
__device__ __forceinline__ float4 f4fma(float a, float4 w, float4 acc) {
    acc.x = fmaf(a, w.x, acc.x); acc.y = fmaf(a, w.y, acc.y);
    acc.z = fmaf(a, w.z, acc.z); acc.w = fmaf(a, w.w, acc.w);
    return acc;
}
__device__ __forceinline__ float4 add4(float4 a, float4 b) {
    return make_float4(a.x+b.x, a.y+b.y, a.z+b.z, a.w+b.w);
}
__device__ __forceinline__ float4 relu6_4(float4 v) {
    v.x = fminf(fmaxf(v.x, 0.f), 6.f); v.y = fminf(fmaxf(v.y, 0.f), 6.f);
    v.z = fminf(fmaxf(v.z, 0.f), 6.f); v.w = fminf(fmaxf(v.w, 0.f), 6.f);
    return v;
}

// ---------------- weight prep: fold BN scales, reorder to [tap][ci][co] ----------------
__global__ void prep_kernel(const float* __restrict__ wv_w, const float* __restrict__ wv_s,
                            const float* __restrict__ wv_b, const float* __restrict__ w3,
                            const float* __restrict__ s3,   const float* __restrict__ b3,
                            const float* __restrict__ wcat, const float* __restrict__ scat,
                            const float* __restrict__ bcat)
{
    int t = blockIdx.x * blockDim.x + threadIdx.x;
    const int N1 = NHn*9*Cn*96, N2 = NHn*9*Cn*64, N3 = NHn*9*Cn*32;
    const int NC = NHn*96*Cn,   NV = CDn*Cn;
    if (t < N1) {
        int co = t % 96; int r = t / 96; int ci = r % 32; r /= 32; int tap = r % 9; int h = r / 9;
        int j = co >> 5, oc = co & 31, ky = tap / 3, kx = tap % 3;
        g_w1[t] = w3[((((h*6 + j)*32 + oc)*32 + ci)*3 + ky)*3 + kx] * s3[(h*6 + j)*32 + oc];
        return;
    } t -= N1;
    if (t < N2) {
        int co = t % 64; int r = t / 64; int ci = r % 32; r /= 32; int tap = r % 9; int h = r / 9;
        int j = 3 + (co >> 5), oc = co & 31, ky = tap / 3, kx = tap % 3;
        g_w2[t] = w3[((((h*6 + j)*32 + oc)*32 + ci)*3 + ky)*3 + kx] * s3[(h*6 + j)*32 + oc];
        return;
    } t -= N2;
    if (t < N3) {
        int co = t % 32; int r = t / 32; int ci = r % 32; r /= 32; int tap = r % 9; int h = r / 9;
        int oc = co, ky = tap / 3, kx = tap % 3;
        g_w3k[t] = w3[((((h*6 + 5)*32 + oc)*32 + ci)*3 + ky)*3 + kx] * s3[(h*6 + 5)*32 + oc];
        return;
    } t -= N3;
    if (t < NC) {
        int co = t & 31; int r = t >> 5; int ci = r % 96; int h = r / 96;
        g_wc[t] = wcat[(h*32 + co)*96 + ci] * scat[h*32 + co];
        return;
    } t -= NC;
    if (t < NV) {
        int co = t & 31; int ci = t >> 5;
        g_wv[t] = wv_w[co*CDn + ci] * wv_s[co];
        return;
    } t -= NV;
    if (t < NHn*96) {
        int co = t % 96; int h = t / 96; int j = co >> 5, oc = co & 31;
        g_b1[t] = b3[(h*6 + j)*32 + oc]; return;
    } t -= NHn*96;
    if (t < NHn*64) {
        int co = t % 64; int h = t / 64; int j = 3 + (co >> 5), oc = co & 31;
        g_b2[t] = b3[(h*6 + j)*32 + oc]; return;
    } t -= NHn*64;
    if (t < NHn*32) {
        int oc = t & 31; int h = t >> 5;
        g_b3k[t] = b3[(h*6 + 5)*32 + oc]; return;
    } t -= NHn*32;
    if (t < NHn*32) { g_bc[t] = bcat[t]; return; }
    t -= NHn*32;
    if (t < Cn) { g_wvb[t] = wv_b[t]; }
}

// ---------------- qp = relu(conv1x1(res) + bias), NCHW -> NHWC ----------------
__global__ void __launch_bounds__(128) qp_kernel(const float* __restrict__ res)
{
    __shared__ __align__(16) float sw[CDn*Cn];
    __shared__ float sb[Cn];
    for (int i = threadIdx.x; i < CDn*Cn; i += 128) sw[i] = g_wv[i];
    if (threadIdx.x < Cn) sb[threadIdx.x] = g_wvb[threadIdx.x];
    __syncthreads();

    int p0 = blockIdx.x * 256 + threadIdx.x;       // 256-px blocks never straddle batch
    int b  = p0 >> 14;  int pix0 = p0 & 16383;
    const float* r0 = res + (size_t)b * CDn * HWn + pix0;

    float4 a0[8], a1[8];
    #pragma unroll
    for (int j = 0; j < 8; j++) { a0[j] = make_float4(0,0,0,0); a1[j] = make_float4(0,0,0,0); }

    for (int ci = 0; ci < CDn; ci++) {
        float x0 = r0[(size_t)ci * HWn];
        float x1 = r0[(size_t)ci * HWn + 128];
        const float4* wr = (const float4*)(sw + ci*Cn);
        #pragma unroll
        for (int j = 0; j < 8; j++) {
            float4 w = wr[j];
            a0[j] = f4fma(x0, w, a0[j]);
            a1[j] = f4fma(x1, w, a1[j]);
        }
    }
    float4* o0 = (float4*)(g_qp + (size_t)p0 * Cn);
    float4* o1 = (float4*)(g_qp + (size_t)(p0 + 128) * Cn);
    #pragma unroll
    for (int j = 0; j < 8; j++) {
        float4 v0 = a0[j], v1 = a1[j];
        v0.x = fmaxf(v0.x + sb[j*4+0], 0.f); v0.y = fmaxf(v0.y + sb[j*4+1], 0.f);
        v0.z = fmaxf(v0.z + sb[j*4+2], 0.f); v0.w = fmaxf(v0.w + sb[j*4+3], 0.f);
        v1.x = fmaxf(v1.x + sb[j*4+0], 0.f); v1.y = fmaxf(v1.y + sb[j*4+1], 0.f);
        v1.z = fmaxf(v1.z + sb[j*4+2], 0.f); v1.w = fmaxf(v1.w + sb[j*4+3], 0.f);
        o0[j] = v0; o1[j] = v1;
    }
}

// ---------------- point attention: dilated 5x5 window, stride 2 ----------------
__global__ void __launch_bounds__(256) pa_kernel()
{
    int p = blockIdx.x * 256 + threadIdx.x;
    int b = p >> 14, pix = p & 16383, h = pix >> 7, w = pix & 127;

    const float4* q4 = (const float4*)g_qp + (size_t)p * 8;
    float4 q[8];
    #pragma unroll
    for (int j = 0; j < 8; j++) q[j] = q4[j];

    float sc[25];
    #pragma unroll
    for (int k = 0; k < 25; k++) {
        int di = (k / 5) * 2 - 4, dj = (k % 5) * 2 - 4;
        int hh = h + di, ww = w + dj;
        float s = 0.f;
        if (k != 12 && hh >= 0 && hh < Hn && ww >= 0 && ww < Wn) {
            const float4* nb = (const float4*)g_qp + (size_t)((b << 14) + (hh << 7) + ww) * 8;
            #pragma unroll
            for (int j = 0; j < 8; j++) {
                float4 v = nb[j];
                s += q[j].x*v.x + q[j].y*v.y + q[j].z*v.z + q[j].w*v.w;
            }
        }
        sc[k] = s;
    }
    float m = sc[0];
    #pragma unroll
    for (int k = 1; k < 25; k++) m = fmaxf(m, sc[k]);
    float Z = 0.f;
    #pragma unroll
    for (int k = 0; k < 25; k++) { sc[k] = __expf(sc[k] - m); Z += sc[k]; }
    float inv = 1.f / Z;

    float4 acc[8];
    #pragma unroll
    for (int j = 0; j < 8; j++) acc[j] = q[j];   // pc = qp + sum_k pa_k * q25_k
    #pragma unroll
    for (int k = 0; k < 25; k++) {
        int di = (k / 5) * 2 - 4, dj = (k % 5) * 2 - 4;
        int hh = h + di, ww = w + dj;
        if (hh >= 0 && hh < Hn && ww >= 0 && ww < Wn) {
            float wgt = sc[k] * inv;
            const float4* nb = (const float4*)g_qp + (size_t)((b << 14) + (hh << 7) + ww) * 8;
            #pragma unroll
            for (int j = 0; j < 8; j++) acc[j] = f4fma(wgt, nb[j], acc[j]);
        }
    }
    float4* o = (float4*)(g_pc + (size_t)p * Cn);
    #pragma unroll
    for (int j = 0; j < 8; j++) o[j] = acc[j];
}

// ---------------- class attention + per-head norm + residual -> xi ----------------
__global__ void __launch_bounds__(256) ca_kernel(const float* __restrict__ attn,
                                                 const float* __restrict__ cn_s,
                                                 const float* __restrict__ cn_b)
{
    int p = blockIdx.x * 256 + threadIdx.x;
    int b = p >> 14, pix = p & 16383;

    float pcf[32];
    const float4* pc4 = (const float4*)g_pc + (size_t)p * 8;
    #pragma unroll
    for (int j = 0; j < 8; j++) {
        float4 v = pc4[j];
        pcf[j*4+0] = v.x; pcf[j*4+1] = v.y; pcf[j*4+2] = v.z; pcf[j*4+3] = v.w;
    }
    float s[8];
    #pragma unroll
    for (int n = 0; n < 8; n++) {
        const float* ap = attn + ((size_t)b * CDn + n * Cn) * HWn + pix;
        float acc = 0.f;
        #pragma unroll
        for (int c = 0; c < 32; c++) acc += pcf[c] * ap[(size_t)c * HWn];
        s[n] = acc;
    }
    float m = s[0];
    #pragma unroll
    for (int n = 1; n < 8; n++) m = fmaxf(m, s[n]);
    float Z = 0.f;
    #pragma unroll
    for (int n = 0; n < 8; n++) { s[n] = __expf(s[n] - m); Z += s[n]; }
    float inv = 1.f / Z;

    #pragma unroll
    for (int n = 0; n < 8; n++) {
        float wn = s[n] * inv;
        const float* ap = attn + ((size_t)b * CDn + n * Cn) * HWn + pix;
        float4* xo = (float4*)(g_xi + ((size_t)(b * NHn + n) * HWn + pix) * Cn);
        #pragma unroll
        for (int c4 = 0; c4 < 8; c4++) {
            float4 o;
            int c = c4 * 4;
            o.x = ap[(size_t)(c+0)*HWn] + wn * pcf[c+0] * __ldg(&cn_s[n*32+c+0]) + __ldg(&cn_b[n*32+c+0]);
            o.y = ap[(size_t)(c+1)*HWn] + wn * pcf[c+1] * __ldg(&cn_s[n*32+c+1]) + __ldg(&cn_b[n*32+c+1]);
            o.z = ap[(size_t)(c+2)*HWn] + wn * pcf[c+2] * __ldg(&cn_s[n*32+c+2]) + __ldg(&cn_b[n*32+c+2]);
            o.w = ap[(size_t)(c+3)*HWn] + wn * pcf[c+3] * __ldg(&cn_s[n*32+c+3]) + __ldg(&cn_b[n*32+c+3]);
            xo[c4] = o;
        }
    }
}

// ---------------- fused MSConv 3x3 stage: conv 32->NOUT, BN(relu6), group-sum ----------------
// S=1: g_xi(32ch)  -> 96-wide -> sum3 -> cat[0:32)
// S=2: cat[0:32)   -> 64-wide -> sum2 -> cat[32:64)
// S=3: cat[32:64)  -> 32-wide        -> cat[64:96)
template <int S>
__global__ void __launch_bounds__(256, 1) conv3x3_kernel()
{
    constexpr int NOUT = (S == 1) ? 96 : (S == 2) ? 64 : 32;
    constexpr int NSUM = (S == 1) ? 3  : (S == 2) ? 2  : 1;
    constexpr int INS  = (S == 1) ? 32 : 96;
    constexpr int INOFF  = (S == 3) ? 32 : 0;
    constexpr int OUTOFF = (S == 1) ? 0 : (S == 2) ? 32 : 64;
    constexpr int NJ = NOUT / 4;

    extern __shared__ float smem[];
    float4*       sX  = (float4*)smem;                       // 8 planes of 18x18 float4
    float4*       sW  = (float4*)(smem + 2592 * 4);          // [tap][ci][co/4]
    const float4* sB4 = (const float4*)(smem + 2592 * 4 + 9 * 32 * NOUT);

    const int img  = blockIdx.y;          // b*8 + n
    const int head = img & 7;
    const int ty0 = (blockIdx.x >> 3) * 16, tx0 = (blockIdx.x & 7) * 16;
    const int tid = threadIdx.x;

    const float* in = (S == 1) ? g_xi : g_cat;
    const float* Wt = (S == 1) ? g_w1 : (S == 2) ? g_w2 : g_w3k;
    const float* Bs = (S == 1) ? g_b1 : (S == 2) ? g_b2 : g_b3k;

    const float4* gw = (const float4*)(Wt + (size_t)head * 9 * 32 * NOUT);
    const int NW = 9 * 32 * NOUT / 4;
    for (int i = tid; i < NW; i += 256) sW[i] = gw[i];
    {
        float* sBf = smem + 2592 * 4 + 9 * 32 * NOUT;
        for (int i = tid; i < NOUT; i += 256) sBf[i] = Bs[head * NOUT + i];
    }
    const float* gin = in + (size_t)img * HWn * INS + INOFF;
    for (int e = tid; e < 2592; e += 256) {
        int c4 = e & 7, pix = e >> 3;
        int iy = pix / 18, ix = pix - iy * 18;
        int hh = ty0 - 1 + iy, ww = tx0 - 1 + ix;
        float4 v = make_float4(0, 0, 0, 0);
        if (hh >= 0 && hh < Hn && ww >= 0 && ww < Wn)
            v = *(const float4*)(gin + (size_t)(hh * Wn + ww) * INS + c4 * 4);
        sX[c4 * 324 + pix] = v;
    }
    __syncthreads();

    const int px = tid & 15, py = tid >> 4;
    float4 acc[NJ];
    #pragma unroll
    for (int j = 0; j < NJ; j++) acc[j] = make_float4(0, 0, 0, 0);

    #pragma unroll 1
    for (int tap = 0; tap < 9; tap++) {
        const int ky = tap / 3, kx = tap - ky * 3;
        const float4* xrow = sX + (py + ky) * 18 + (px + kx);
        const float4* wt = sW + tap * (32 * NJ);
        #pragma unroll 1
        for (int c4 = 0; c4 < 8; c4++) {
            float4 xv = xrow[c4 * 324];
            const float4* w0 = wt + (c4 * 4) * NJ;
            #pragma unroll
            for (int j = 0; j < NJ; j++) {
                float4 wa = w0[j], wb = w0[NJ + j], wcx = w0[2 * NJ + j], wd = w0[3 * NJ + j];
                acc[j] = f4fma(xv.x, wa,  acc[j]);
                acc[j] = f4fma(xv.y, wb,  acc[j]);
                acc[j] = f4fma(xv.z, wcx, acc[j]);
                acc[j] = f4fma(xv.w, wd,  acc[j]);
            }
        }
    }

    float* gout = g_cat + ((size_t)img * HWn + (ty0 + py) * Wn + (tx0 + px)) * 96 + OUTOFF;
    #pragma unroll
    for (int j = 0; j < 8; j++) {
        float4 sum = relu6_4(add4(acc[j], sB4[j]));
        if (NSUM > 1) sum = add4(sum, relu6_4(add4(acc[8 + j],  sB4[8 + j])));
        if (NSUM > 2) sum = add4(sum, relu6_4(add4(acc[16 + j], sB4[16 + j])));
        *(float4*)(gout + j * 4) = sum;
    }
}

// ---------------- 1x1 conv 96->32 + bias + residual(xi) + relu -> NCHW out ----------------
__global__ void __launch_bounds__(256) final_kernel(float* __restrict__ out)
{
    __shared__ __align__(16) float sw[96 * 32];
    __shared__ float sb[32];
    const int img = blockIdx.y, head = img & 7;
    const float* gw = g_wc + (size_t)head * 96 * 32;
    for (int i = threadIdx.x; i < 96 * 32; i += 256) sw[i] = gw[i];
    if (threadIdx.x < 32) sb[threadIdx.x] = g_bc[head * 32 + threadIdx.x];
    __syncthreads();

    const int p = blockIdx.x * 256 + threadIdx.x;   // pixel in image
    const float4* cv = (const float4*)(g_cat + ((size_t)img * HWn + p) * 96);

    float4 acc[8];
    #pragma unroll
    for (int j = 0; j < 8; j++) acc[j] = make_float4(0, 0, 0, 0);

    #pragma unroll 1
    for (int ci4 = 0; ci4 < 24; ci4++) {
        float4 x = cv[ci4];
        const float4* w0 = (const float4*)(sw + (ci4 * 4 + 0) * 32);
        const float4* w1 = (const float4*)(sw + (ci4 * 4 + 1) * 32);
        const float4* w2 = (const float4*)(sw + (ci4 * 4 + 2) * 32);
        const float4* w3p = (const float4*)(sw + (ci4 * 4 + 3) * 32);
        #pragma unroll
        for (int j = 0; j < 8; j++) {
            acc[j] = f4fma(x.x, w0[j], acc[j]);
            acc[j] = f4fma(x.y, w1[j], acc[j]);
            acc[j] = f4fma(x.z, w2[j], acc[j]);
            acc[j] = f4fma(x.w, w3p[j], acc[j]);
        }
    }
    const float4* xiv = (const float4*)(g_xi + ((size_t)img * HWn + p) * Cn);
    #pragma unroll
    for (int j = 0; j < 8; j++) {
        float4 xr = xiv[j];
        float ox = fmaxf(acc[j].x + sb[j*4+0] + xr.x, 0.f);
        float oy = fmaxf(acc[j].y + sb[j*4+1] + xr.y, 0.f);
        float oz = fmaxf(acc[j].z + sb[j*4+2] + xr.z, 0.f);
        float ow = fmaxf(acc[j].w + sb[j*4+3] + xr.w, 0.f);
        size_t base = (size_t)(img * 32 + j * 4) * HWn + p;
        out[base]           = ox;
        out[base + HWn]     = oy;
        out[base + 2*HWn]   = oz;
        out[base + 3*HWn]   = ow;
    }
}

// ---------------- launch ----------------
extern "C" void kernel_launch(void* const* d_in, const int* in_sizes, int n_in,
                              void* d_out, int out_size)
{
    (void)in_sizes; (void)n_in; (void)out_size;
    const float* res  = (const float*)d_in[0];
    const float* attn = (const float*)d_in[1];
    const float* wv_w = (const float*)d_in[2];
    const float* wv_s = (const float*)d_in[3];
    const float* wv_b = (const float*)d_in[4];
    const float* cn_s = (const float*)d_in[5];
    const float* cn_b = (const float*)d_in[6];
    const float* w3   = (const float*)d_in[7];
    const float* s3   = (const float*)d_in[8];
    const float* b3   = (const float*)d_in[9];
    const float* wcat = (const float*)d_in[10];
    const float* scat = (const float*)d_in[11];
    const float* bcat = (const float*)d_in[12];
    float* out = (float*)d_out;

    const int smem1 = (2592 * 4 + 9 * 32 * 96 + 96) * 4;   // 152448
    const int smem2 = (2592 * 4 + 9 * 32 * 64 + 64) * 4;   // 115456
    const int smem3 = (2592 * 4 + 9 * 32 * 32 + 32) * 4;   //  78464
    cudaFuncSetAttribute(conv3x3_kernel<1>, cudaFuncAttributeMaxDynamicSharedMemorySize, smem1);
    cudaFuncSetAttribute(conv3x3_kernel<2>, cudaFuncAttributeMaxDynamicSharedMemorySize, smem2);
    cudaFuncSetAttribute(conv3x3_kernel<3>, cudaFuncAttributeMaxDynamicSharedMemorySize, smem3);

    prep_kernel<<<1864, 256>>>(wv_w, wv_s, wv_b, w3, s3, b3, wcat, scat, bcat);
    qp_kernel<<<256, 128>>>(res);
    pa_kernel<<<256, 256>>>();
    ca_kernel<<<256, 256>>>(attn, cn_s, cn_b);
    conv3x3_kernel<1><<<dim3(64, 32), 256, smem1>>>();
    conv3x3_kernel<2><<<dim3(64, 32), 256, smem2>>>();
    conv3x3_kernel<3><<<dim3(64, 32), 256, smem3>>>();
    final_kernel<<<dim3(64, 32), 256>>>(out);
}